// round 14
// baseline (speedup 1.0000x reference)
#include <cuda_runtime.h>
#include <cuda_fp16.h>
#include <cstdint>

#define FEATURE_COUNT 106496LL
#define ACCUM 256
#define LEAK 0.1f
#define NSTAGE 6
#define PF 4
#define GRID_MAIN 296           // 2 blocks/SM on 148-SM B200
#define TMA_NUM 11              // TMA role gets n*11/28 of each chunk

// fp16 copy of the embedding table (54.5 MB module-static scratch)
__device__ __align__(16) __half g_embed_h[FEATURE_COUNT * ACCUM];

__device__ __forceinline__ long long geti(const void* p, long long i, int is64) {
    return is64 ? ((const long long*)p)[i] : (long long)((const int*)p)[i];
}

__device__ __forceinline__ float clipped_relu(float x) {
    float c = fminf(fmaxf(x, -1.0f), 127.0f / 128.0f);
    return c + LEAK * (x - c);
}

__device__ __forceinline__ uint32_t smem_u32(const void* p) {
    uint32_t a;
    asm("{ .reg .u64 t; cvta.to.shared.u64 t, %1; cvt.u32.u64 %0, t; }"
        : "=r"(a) : "l"(p));
    return a;
}

#define BARX(id, cnt) asm volatile("bar.sync %0, %1;" :: "r"(id), "r"(cnt) : "memory")

__device__ __forceinline__ void mbar_wait(uint32_t mbar, int par) {
    uint32_t done;
    asm volatile(
        "{\n\t.reg .pred p;\n\t"
        "mbarrier.try_wait.parity.acquire.cta.shared::cta.b64 p, [%1], %2;\n\t"
        "selp.b32 %0, 1, 0, p;\n\t}"
        : "=r"(done) : "r"(mbar), "r"(par) : "memory");
    while (!done)
        asm volatile(
            "{\n\t.reg .pred p;\n\t"
            "mbarrier.try_wait.parity.acquire.cta.shared::cta.b64 p, [%1], %2, 0x989680;\n\t"
            "selp.b32 %0, 1, 0, p;\n\t}"
            : "=r"(done) : "r"(mbar), "r"(par) : "memory");
}

// ---------------------------------------------------------------------------
// Streaming f32 -> fp16 table conversion (runs every launch; ~164MB at DRAM
// speed while DRAM is otherwise 83% idle).
// ---------------------------------------------------------------------------
__global__ __launch_bounds__(256) void convert_kernel(const float* __restrict__ embed) {
    const long long total4 = (FEATURE_COUNT * ACCUM) / 4;
    const float4* __restrict__ e4 = (const float4*)embed;
    uint2* __restrict__ dst = (uint2*)g_embed_h;
    for (long long i = blockIdx.x * (long long)blockDim.x + threadIdx.x;
         i < total4; i += (long long)gridDim.x * blockDim.x) {
        float4 v = e4[i];
        __half2 a = __floats2half2_rn(v.x, v.y);
        __half2 b = __floats2half2_rn(v.z, v.w);
        uint2 u;
        u.x = *(uint32_t*)&a;
        u.y = *(uint32_t*)&b;
        dst[i] = u;
    }
}

// ---------------------------------------------------------------------------
// Hybrid kernel (R6 structure) on the fp16 table: every gathered row is now
// 512B = 4 cache lines instead of 8 -> halves the per-SM outstanding-line
// demand that all seven prior experiments identified as the wall.
//   t in [0,256): TMA role — 6-stage cp.async.bulk pipeline (512B rows)
//   t in [256,384): LDG role — two 64-thread groups, uint2 (4 cols) per lane
// ---------------------------------------------------------------------------
extern __shared__ __align__(16) __half s_stage_h[];   // NSTAGE*32*256 halves = 96KB

__global__ __launch_bounds__(384, 2) void nnue_fused(
    const void*  __restrict__ indices,
    const void*  __restrict__ offsets,
    const void*  __restrict__ which_model,
    const void*  __restrict__ lengths,
    const float* __restrict__ bias,
    const float* __restrict__ W1, const float* __restrict__ b1,
    const float* __restrict__ W2, const float* __restrict__ b2,
    const float* __restrict__ W3, const float* __restrict__ b3,
    float* __restrict__ out,
    long long n_idx, int B)
{
    __shared__ __align__(8)  unsigned long long s_mbar[NSTAGE];
    __shared__ __align__(16) float  s_embT[ACCUM];
    __shared__ __align__(16) float  s_h1T[16];
    __shared__ __align__(16) float4 s_embL[2][64];
    __shared__ __align__(16) float  s_h1L[2][16];
    __shared__ float s_psqtT, s_psqtL[2];
    __shared__ int   s_is64;

    const int t = threadIdx.x;
    const int chunk = (B + (int)gridDim.x - 1) / (int)gridDim.x;
    const int beg = blockIdx.x * chunk;
    const int end = min(beg + chunk, B);
    const int n = end - beg;
    if (n <= 0) return;
    const int nT = (n * TMA_NUM) / 28;   // TMA role's share of the chunk

    // dtype detection (one warp, one ballot) + mbarrier init
    if (t < 32) {
        int ok = 1;
        if (t < 16) {
            long long v = ((const long long*)indices)[t];
            ok = (v >= 0 && v < FEATURE_COUNT);
        }
        unsigned m = __ballot_sync(0xffffffffu, ok);
        if (t == 0) {
            s_is64 = (m == 0xffffffffu) ? 1 : 0;
            #pragma unroll
            for (int s = 0; s < NSTAGE; s++)
                asm volatile("mbarrier.init.shared.b64 [%0], %1;"
                             :: "r"(smem_u32(&s_mbar[s])), "r"(1) : "memory");
        }
    }
    __syncthreads();
    const int is64 = s_is64;

    if (t < 256) {
        // ================= TMA role: batches [beg, beg+nT) =================
        const uint32_t stage_base = smem_u32(s_stage_h);

        auto issue = [&](int i) {
            const int b = beg + i;
            const long long lo = geti(offsets, b, is64);
            const long long hi = (b + 1 < B) ? geti(offsets, b + 1, is64) : n_idx;
            const int st = min((int)(hi - lo), 32);
            const int s = i % NSTAGE;
            const uint32_t mbar = smem_u32(&s_mbar[s]);
            if (t == 0)
                asm volatile("mbarrier.arrive.expect_tx.shared.b64 _, [%0], %1;"
                             :: "r"(mbar), "r"((unsigned)(st * 512)) : "memory");
            __syncwarp();
            if (t < st) {
                long long id = geti(indices, lo + t, is64);
                const __half* src = g_embed_h + id * ACCUM;
                uint32_t dst = stage_base + (uint32_t)s * 16384u + (uint32_t)t * 512u;
                asm volatile(
                    "cp.async.bulk.shared::cta.global.mbarrier::complete_tx::bytes "
                    "[%0], [%1], %2, [%3];"
                    :: "r"(dst), "l"(src), "r"(512), "r"(mbar) : "memory");
            }
        };

        if (t < 32) {
            const int pro = min(PF, nT);
            for (int j = 0; j < pro; j++) issue(j);
        }

        for (int i = 0; i < nT; i++) {
            if (t < 32 && i + PF < nT) issue(i + PF);

            mbar_wait(smem_u32(&s_mbar[i % NSTAGE]), (i / NSTAGE) & 1);

            const int b = beg + i;
            const long long lo = geti(offsets, b, is64);
            const long long hi = (b + 1 < B) ? geti(offsets, b + 1, is64) : n_idx;
            const int cnt = (int)(hi - lo);
            const int staged = min(cnt, 32);
            const __half* __restrict__ st_base = s_stage_h + (i % NSTAGE) * (32 * ACCUM);

            float a0 = bias[t], a1 = 0.0f;
            if (staged == 32) {
                #pragma unroll
                for (int r = 0; r < 32; r += 2) {
                    a0 += __half2float(st_base[r * ACCUM + t]);
                    a1 += __half2float(st_base[(r + 1) * ACCUM + t]);
                }
            } else {
                for (int r = 0; r < staged; r++)
                    a0 += __half2float(st_base[r * ACCUM + t]);
            }
            for (int r = 32; r < cnt; r++) {      // safety tail (L=32: unused)
                long long id = geti(indices, lo + r, is64);
                a0 += __half2float(g_embed_h[id * ACCUM + t]);
            }
            float acc = a0 + a1;

            if (t == 0) s_psqtT = acc;            // pre-activation column 0
            s_embT[t] = clipped_relu(acc);
            BARX(3, 256);

            const int sel = (int)geti(which_model, b, is64)
                          + ((int)geti(lengths, b, is64) / 17) * 4;

            // layer 1: 16 outputs x 16 lanes
            {
                const int o = t >> 4;
                const int k = t & 15;
                const float4* __restrict__ w =
                    (const float4*)(W1 + ((long long)sel * 16 + o) * ACCUM) + k * 4;
                const float4* __restrict__ e = (const float4*)s_embT + k * 4;
                float s = 0.0f;
                #pragma unroll
                for (int j = 0; j < 4; j++) {
                    float4 wv = w[j], ev = e[j];
                    s += wv.x * ev.x + wv.y * ev.y + wv.z * ev.z + wv.w * ev.w;
                }
                s += __shfl_xor_sync(0xffffffffu, s, 1);
                s += __shfl_xor_sync(0xffffffffu, s, 2);
                s += __shfl_xor_sync(0xffffffffu, s, 4);
                s += __shfl_xor_sync(0xffffffffu, s, 8);
                if (k == 0) s_h1T[o] = clipped_relu(s + b1[sel * 16 + o]);
            }
            BARX(3, 256);

            if (t < 32) {                         // layers 2+3 + epilogue
                const float4* __restrict__ w2 =
                    (const float4*)(W2 + ((long long)sel * 32 + t) * 16);
                float4 h0 = ((const float4*)s_h1T)[0];
                float4 h1v = ((const float4*)s_h1T)[1];
                float4 h2v = ((const float4*)s_h1T)[2];
                float4 h3v = ((const float4*)s_h1T)[3];
                float4 wa = w2[0], wb = w2[1], wc = w2[2], wd = w2[3];
                float s = b2[sel * 32 + t]
                    + wa.x * h0.x + wa.y * h0.y + wa.z * h0.z + wa.w * h0.w
                    + wb.x * h1v.x + wb.y * h1v.y + wb.z * h1v.z + wb.w * h1v.w
                    + wc.x * h2v.x + wc.y * h2v.y + wc.z * h2v.z + wc.w * h2v.w
                    + wd.x * h3v.x + wd.y * h3v.y + wd.z * h3v.z + wd.w * h3v.w;
                float p = clipped_relu(s) * W3[sel * 32 + t];
                #pragma unroll
                for (int off = 16; off > 0; off >>= 1)
                    p += __shfl_xor_sync(0xffffffffu, p, off);
                if (t == 0) out[b] = tanhf(p + b3[sel] + s_psqtT);
            }
        }
    } else {
        // ============ LDG role: batches [beg+nT, end), 2 groups ============
        const int gt   = t - 256;      // 0..127
        const int grp  = gt >> 6;      // 0 or 1
        const int lane = gt & 63;      // lane within the 64-thread group
        const int wl   = gt & 31;      // lane within warp
        const int barid = 1 + grp;

        for (int b = beg + nT + grp; b < end; b += 2) {
            const long long lo = geti(offsets, b, is64);
            const long long hi = (b + 1 < B) ? geti(offsets, b + 1, is64) : n_idx;
            const int cnt = (int)(hi - lo);
            const int pre = min(cnt, 32);

            // preload indices: each warp holds all 32 ids in registers
            int myid = 0;
            if (wl < pre) myid = (int)geti(indices, lo + wl, is64);

            // lane owns 4 columns [4*lane, 4*lane+4): one uint2 (8B) per row
            float4 acc = ((const float4*)bias)[lane];
            if (pre == 32) {
                #pragma unroll 8
                for (int r = 0; r < 32; r++) {
                    int id = __shfl_sync(0xffffffffu, myid, r);
                    uint2 u = *((const uint2*)(g_embed_h + (long long)id * ACCUM) + lane);
                    float2 f0 = __half22float2(*(__half2*)&u.x);
                    float2 f1 = __half22float2(*(__half2*)&u.y);
                    acc.x += f0.x; acc.y += f0.y; acc.z += f1.x; acc.w += f1.y;
                }
            } else {
                for (int r = 0; r < pre; r++) {
                    int id = __shfl_sync(0xffffffffu, myid, r);
                    uint2 u = *((const uint2*)(g_embed_h + (long long)id * ACCUM) + lane);
                    float2 f0 = __half22float2(*(__half2*)&u.x);
                    float2 f1 = __half22float2(*(__half2*)&u.y);
                    acc.x += f0.x; acc.y += f0.y; acc.z += f1.x; acc.w += f1.y;
                }
            }
            for (long long j = lo + 32; j < hi; j++) {   // safety tail
                long long id = geti(indices, j, is64);
                uint2 u = *((const uint2*)(g_embed_h + id * ACCUM) + lane);
                float2 f0 = __half22float2(*(__half2*)&u.x);
                float2 f1 = __half22float2(*(__half2*)&u.y);
                acc.x += f0.x; acc.y += f0.y; acc.z += f1.x; acc.w += f1.y;
            }

            if (lane == 0) s_psqtL[grp] = acc.x;  // pre-activation column 0
            s_embL[grp][lane] = make_float4(clipped_relu(acc.x), clipped_relu(acc.y),
                                            clipped_relu(acc.z), clipped_relu(acc.w));
            BARX(barid, 64);

            const int sel = (int)geti(which_model, b, is64)
                          + ((int)geti(lengths, b, is64) / 17) * 4;

            // layer 1: 16 outputs x 4 lanes (shuffle partners share a warp)
            {
                const int o = lane >> 2;
                const int k = lane & 3;
                const float4* __restrict__ w =
                    (const float4*)(W1 + ((long long)sel * 16 + o) * ACCUM) + k * 16;
                const float4* __restrict__ e = &s_embL[grp][0] + k * 16;
                float s = 0.0f;
                #pragma unroll
                for (int j = 0; j < 16; j++) {
                    float4 wv = w[j], ev = e[j];
                    s += wv.x * ev.x + wv.y * ev.y + wv.z * ev.z + wv.w * ev.w;
                }
                s += __shfl_xor_sync(0xffffffffu, s, 1);
                s += __shfl_xor_sync(0xffffffffu, s, 2);
                if (k == 0) s_h1L[grp][o] = clipped_relu(s + b1[sel * 16 + o]);
            }
            BARX(barid, 64);

            if (lane < 32) {                      // layers 2+3 + epilogue
                const float4* __restrict__ w2 =
                    (const float4*)(W2 + ((long long)sel * 32 + lane) * 16);
                float4 h0 = ((const float4*)s_h1L[grp])[0];
                float4 h1v = ((const float4*)s_h1L[grp])[1];
                float4 h2v = ((const float4*)s_h1L[grp])[2];
                float4 h3v = ((const float4*)s_h1L[grp])[3];
                float4 wa = w2[0], wb = w2[1], wc = w2[2], wd = w2[3];
                float s = b2[sel * 32 + lane]
                    + wa.x * h0.x + wa.y * h0.y + wa.z * h0.z + wa.w * h0.w
                    + wb.x * h1v.x + wb.y * h1v.y + wb.z * h1v.z + wb.w * h1v.w
                    + wc.x * h2v.x + wc.y * h2v.y + wc.z * h2v.z + wc.w * h2v.w
                    + wd.x * h3v.x + wd.y * h3v.y + wd.z * h3v.z + wd.w * h3v.w;
                float p = clipped_relu(s) * W3[sel * 32 + lane];
                #pragma unroll
                for (int off = 16; off > 0; off >>= 1)
                    p += __shfl_xor_sync(0xffffffffu, p, off);
                if (lane == 0) out[b] = tanhf(p + b3[sel] + s_psqtL[grp]);
            }
            // warp B reaches its next s_h1L write only after the next BARX,
            // which warp A joins after finishing layers 2+3 here.
        }
    }
}

extern "C" void kernel_launch(void* const* d_in, const int* in_sizes, int n_in,
                              void* d_out, int out_size) {
    const void*  indices     = d_in[0];
    const void*  offsets     = d_in[1];
    const void*  which_model = d_in[2];
    const void*  lengths     = d_in[3];
    const float* embed       = (const float*)d_in[4];
    const float* bias        = (const float*)d_in[5];
    const float* W1 = (const float*)d_in[6];
    const float* b1 = (const float*)d_in[7];
    const float* W2 = (const float*)d_in[8];
    const float* b2 = (const float*)d_in[9];
    const float* W3 = (const float*)d_in[10];
    const float* b3 = (const float*)d_in[11];

    long long n_idx = in_sizes[0];
    int B = in_sizes[1];

    const int dyn_smem = NSTAGE * 32 * ACCUM * (int)sizeof(__half);  // 96KB
    cudaFuncSetAttribute(nnue_fused,
                         cudaFuncAttributeMaxDynamicSharedMemorySize,
                         dyn_smem);

    convert_kernel<<<2048, 256>>>(embed);
    nnue_fused<<<GRID_MAIN, 384, dyn_smem>>>(indices, offsets, which_model,
                                             lengths, bias,
                                             W1, b1, W2, b2, W3, b3,
                                             (float*)d_out, n_idx, B);
}

// round 16
// speedup vs baseline: 1.0638x; 1.0638x over previous
#include <cuda_runtime.h>
#include <cuda_fp16.h>
#include <cstdint>

#define FEATURE_COUNT 106496LL
#define ACCUM 256
#define LEAK 0.1f
#define NSTAGE 6
#define PF 4
#define GRID_MAIN 296           // 2 blocks/SM on 148-SM B200
#define TMA_NUM 11              // TMA role gets n*11/28 of each chunk

// fp16 copy of the embedding table (54.5 MB module-static scratch)
__device__ __align__(16) __half g_embed_h[FEATURE_COUNT * ACCUM];

__device__ __forceinline__ long long geti(const void* p, long long i, int is64) {
    return is64 ? ((const long long*)p)[i] : (long long)((const int*)p)[i];
}

__device__ __forceinline__ float clipped_relu(float x) {
    float c = fminf(fmaxf(x, -1.0f), 127.0f / 128.0f);
    return c + LEAK * (x - c);
}

__device__ __forceinline__ uint32_t smem_u32(const void* p) {
    uint32_t a;
    asm("{ .reg .u64 t; cvta.to.shared.u64 t, %1; cvt.u32.u64 %0, t; }"
        : "=r"(a) : "l"(p));
    return a;
}

#define BARX(id, cnt) asm volatile("bar.sync %0, %1;" :: "r"(id), "r"(cnt) : "memory")

__device__ __forceinline__ void mbar_wait(uint32_t mbar, int par) {
    uint32_t done;
    asm volatile(
        "{\n\t.reg .pred p;\n\t"
        "mbarrier.try_wait.parity.acquire.cta.shared::cta.b64 p, [%1], %2;\n\t"
        "selp.b32 %0, 1, 0, p;\n\t}"
        : "=r"(done) : "r"(mbar), "r"(par) : "memory");
    while (!done)
        asm volatile(
            "{\n\t.reg .pred p;\n\t"
            "mbarrier.try_wait.parity.acquire.cta.shared::cta.b64 p, [%1], %2, 0x989680;\n\t"
            "selp.b32 %0, 1, 0, p;\n\t}"
            : "=r"(done) : "r"(mbar), "r"(par) : "memory");
}

// ---------------------------------------------------------------------------
// Streaming f32 -> fp16 table conversion.
// KEY: the f32 reads use an L2 evict_first policy so the 109MB stream does
// NOT flush L2 — the 54.5MB of fp16 writes (write-allocate) stay resident,
// and the main kernel's whole gather is then served at L2-hit latency.
// ---------------------------------------------------------------------------
__global__ __launch_bounds__(256) void convert_kernel(const float* __restrict__ embed) {
    uint64_t pol;
    asm("createpolicy.fractional.L2::evict_first.b64 %0, 1.0;" : "=l"(pol));
    const long long total4 = (FEATURE_COUNT * ACCUM) / 4;
    const float4* __restrict__ e4 = (const float4*)embed;
    uint2* __restrict__ dst = (uint2*)g_embed_h;
    for (long long i = blockIdx.x * (long long)blockDim.x + threadIdx.x;
         i < total4; i += (long long)gridDim.x * blockDim.x) {
        float4 v;
        asm("ld.global.L2::cache_hint.v4.f32 {%0,%1,%2,%3}, [%4], %5;"
            : "=f"(v.x), "=f"(v.y), "=f"(v.z), "=f"(v.w)
            : "l"(e4 + i), "l"(pol));
        __half2 a = __floats2half2_rn(v.x, v.y);
        __half2 b = __floats2half2_rn(v.z, v.w);
        uint2 u;
        u.x = *(uint32_t*)&a;
        u.y = *(uint32_t*)&b;
        dst[i] = u;
    }
}

// ---------------------------------------------------------------------------
// Hybrid kernel (R6 structure) on the fp16 table (rows 512B).
//   t in [0,256): TMA role — 6-stage cp.async.bulk pipeline (512B rows)
//   t in [256,384): LDG role — two 64-thread groups, uint2 (4 cols) per lane
// With the fp16 table L2-resident (see convert), the gather runs at L2 tier.
// ---------------------------------------------------------------------------
extern __shared__ __align__(16) __half s_stage_h[];   // NSTAGE*32*256 halves = 96KB

__global__ __launch_bounds__(384, 2) void nnue_fused(
    const void*  __restrict__ indices,
    const void*  __restrict__ offsets,
    const void*  __restrict__ which_model,
    const void*  __restrict__ lengths,
    const float* __restrict__ bias,
    const float* __restrict__ W1, const float* __restrict__ b1,
    const float* __restrict__ W2, const float* __restrict__ b2,
    const float* __restrict__ W3, const float* __restrict__ b3,
    float* __restrict__ out,
    long long n_idx, int B)
{
    __shared__ __align__(8)  unsigned long long s_mbar[NSTAGE];
    __shared__ __align__(16) float  s_embT[ACCUM];
    __shared__ __align__(16) float  s_h1T[16];
    __shared__ __align__(16) float4 s_embL[2][64];
    __shared__ __align__(16) float  s_h1L[2][16];
    __shared__ float s_psqtT, s_psqtL[2];
    __shared__ int   s_is64;

    const int t = threadIdx.x;
    const int chunk = (B + (int)gridDim.x - 1) / (int)gridDim.x;
    const int beg = blockIdx.x * chunk;
    const int end = min(beg + chunk, B);
    const int n = end - beg;
    if (n <= 0) return;
    const int nT = (n * TMA_NUM) / 28;   // TMA role's share of the chunk

    // dtype detection (one warp, one ballot) + mbarrier init
    if (t < 32) {
        int ok = 1;
        if (t < 16) {
            long long v = ((const long long*)indices)[t];
            ok = (v >= 0 && v < FEATURE_COUNT);
        }
        unsigned m = __ballot_sync(0xffffffffu, ok);
        if (t == 0) {
            s_is64 = (m == 0xffffffffu) ? 1 : 0;
            #pragma unroll
            for (int s = 0; s < NSTAGE; s++)
                asm volatile("mbarrier.init.shared.b64 [%0], %1;"
                             :: "r"(smem_u32(&s_mbar[s])), "r"(1) : "memory");
        }
    }
    __syncthreads();
    const int is64 = s_is64;

    if (t < 256) {
        // ================= TMA role: batches [beg, beg+nT) =================
        const uint32_t stage_base = smem_u32(s_stage_h);

        auto issue = [&](int i) {
            const int b = beg + i;
            const long long lo = geti(offsets, b, is64);
            const long long hi = (b + 1 < B) ? geti(offsets, b + 1, is64) : n_idx;
            const int st = min((int)(hi - lo), 32);
            const int s = i % NSTAGE;
            const uint32_t mbar = smem_u32(&s_mbar[s]);
            if (t == 0)
                asm volatile("mbarrier.arrive.expect_tx.shared.b64 _, [%0], %1;"
                             :: "r"(mbar), "r"((unsigned)(st * 512)) : "memory");
            __syncwarp();
            if (t < st) {
                long long id = geti(indices, lo + t, is64);
                const __half* src = g_embed_h + id * ACCUM;
                uint32_t dst = stage_base + (uint32_t)s * 16384u + (uint32_t)t * 512u;
                asm volatile(
                    "cp.async.bulk.shared::cta.global.mbarrier::complete_tx::bytes "
                    "[%0], [%1], %2, [%3];"
                    :: "r"(dst), "l"(src), "r"(512), "r"(mbar) : "memory");
            }
        };

        if (t < 32) {
            const int pro = min(PF, nT);
            for (int j = 0; j < pro; j++) issue(j);
        }

        for (int i = 0; i < nT; i++) {
            if (t < 32 && i + PF < nT) issue(i + PF);

            mbar_wait(smem_u32(&s_mbar[i % NSTAGE]), (i / NSTAGE) & 1);

            const int b = beg + i;
            const long long lo = geti(offsets, b, is64);
            const long long hi = (b + 1 < B) ? geti(offsets, b + 1, is64) : n_idx;
            const int cnt = (int)(hi - lo);
            const int staged = min(cnt, 32);
            const __half* __restrict__ st_base = s_stage_h + (i % NSTAGE) * (32 * ACCUM);

            float a0 = bias[t], a1 = 0.0f;
            if (staged == 32) {
                #pragma unroll
                for (int r = 0; r < 32; r += 2) {
                    a0 += __half2float(st_base[r * ACCUM + t]);
                    a1 += __half2float(st_base[(r + 1) * ACCUM + t]);
                }
            } else {
                for (int r = 0; r < staged; r++)
                    a0 += __half2float(st_base[r * ACCUM + t]);
            }
            for (int r = 32; r < cnt; r++) {      // safety tail (L=32: unused)
                long long id = geti(indices, lo + r, is64);
                a0 += __half2float(g_embed_h[id * ACCUM + t]);
            }
            float acc = a0 + a1;

            if (t == 0) s_psqtT = acc;            // pre-activation column 0
            s_embT[t] = clipped_relu(acc);
            BARX(3, 256);

            const int sel = (int)geti(which_model, b, is64)
                          + ((int)geti(lengths, b, is64) / 17) * 4;

            // layer 1: 16 outputs x 16 lanes
            {
                const int o = t >> 4;
                const int k = t & 15;
                const float4* __restrict__ w =
                    (const float4*)(W1 + ((long long)sel * 16 + o) * ACCUM) + k * 4;
                const float4* __restrict__ e = (const float4*)s_embT + k * 4;
                float s = 0.0f;
                #pragma unroll
                for (int j = 0; j < 4; j++) {
                    float4 wv = w[j], ev = e[j];
                    s += wv.x * ev.x + wv.y * ev.y + wv.z * ev.z + wv.w * ev.w;
                }
                s += __shfl_xor_sync(0xffffffffu, s, 1);
                s += __shfl_xor_sync(0xffffffffu, s, 2);
                s += __shfl_xor_sync(0xffffffffu, s, 4);
                s += __shfl_xor_sync(0xffffffffu, s, 8);
                if (k == 0) s_h1T[o] = clipped_relu(s + b1[sel * 16 + o]);
            }
            BARX(3, 256);

            if (t < 32) {                         // layers 2+3 + epilogue
                const float4* __restrict__ w2 =
                    (const float4*)(W2 + ((long long)sel * 32 + t) * 16);
                float4 h0 = ((const float4*)s_h1T)[0];
                float4 h1v = ((const float4*)s_h1T)[1];
                float4 h2v = ((const float4*)s_h1T)[2];
                float4 h3v = ((const float4*)s_h1T)[3];
                float4 wa = w2[0], wb = w2[1], wc = w2[2], wd = w2[3];
                float s = b2[sel * 32 + t]
                    + wa.x * h0.x + wa.y * h0.y + wa.z * h0.z + wa.w * h0.w
                    + wb.x * h1v.x + wb.y * h1v.y + wb.z * h1v.z + wb.w * h1v.w
                    + wc.x * h2v.x + wc.y * h2v.y + wc.z * h2v.z + wc.w * h2v.w
                    + wd.x * h3v.x + wd.y * h3v.y + wd.z * h3v.z + wd.w * h3v.w;
                float p = clipped_relu(s) * W3[sel * 32 + t];
                #pragma unroll
                for (int off = 16; off > 0; off >>= 1)
                    p += __shfl_xor_sync(0xffffffffu, p, off);
                if (t == 0) out[b] = tanhf(p + b3[sel] + s_psqtT);
            }
        }
    } else {
        // ============ LDG role: batches [beg+nT, end), 2 groups ============
        const int gt   = t - 256;      // 0..127
        const int grp  = gt >> 6;      // 0 or 1
        const int lane = gt & 63;      // lane within the 64-thread group
        const int wl   = gt & 31;      // lane within warp
        const int barid = 1 + grp;

        for (int b = beg + nT + grp; b < end; b += 2) {
            const long long lo = geti(offsets, b, is64);
            const long long hi = (b + 1 < B) ? geti(offsets, b + 1, is64) : n_idx;
            const int cnt = (int)(hi - lo);
            const int pre = min(cnt, 32);

            // preload indices: each warp holds all 32 ids in registers
            int myid = 0;
            if (wl < pre) myid = (int)geti(indices, lo + wl, is64);

            // lane owns 4 columns [4*lane, 4*lane+4): one uint2 (8B) per row
            float4 acc = ((const float4*)bias)[lane];
            if (pre == 32) {
                #pragma unroll 8
                for (int r = 0; r < 32; r++) {
                    int id = __shfl_sync(0xffffffffu, myid, r);
                    uint2 u = *((const uint2*)(g_embed_h + (long long)id * ACCUM) + lane);
                    float2 f0 = __half22float2(*(__half2*)&u.x);
                    float2 f1 = __half22float2(*(__half2*)&u.y);
                    acc.x += f0.x; acc.y += f0.y; acc.z += f1.x; acc.w += f1.y;
                }
            } else {
                for (int r = 0; r < pre; r++) {
                    int id = __shfl_sync(0xffffffffu, myid, r);
                    uint2 u = *((const uint2*)(g_embed_h + (long long)id * ACCUM) + lane);
                    float2 f0 = __half22float2(*(__half2*)&u.x);
                    float2 f1 = __half22float2(*(__half2*)&u.y);
                    acc.x += f0.x; acc.y += f0.y; acc.z += f1.x; acc.w += f1.y;
                }
            }
            for (long long j = lo + 32; j < hi; j++) {   // safety tail
                long long id = geti(indices, j, is64);
                uint2 u = *((const uint2*)(g_embed_h + id * ACCUM) + lane);
                float2 f0 = __half22float2(*(__half2*)&u.x);
                float2 f1 = __half22float2(*(__half2*)&u.y);
                acc.x += f0.x; acc.y += f0.y; acc.z += f1.x; acc.w += f1.y;
            }

            if (lane == 0) s_psqtL[grp] = acc.x;  // pre-activation column 0
            s_embL[grp][lane] = make_float4(clipped_relu(acc.x), clipped_relu(acc.y),
                                            clipped_relu(acc.z), clipped_relu(acc.w));
            BARX(barid, 64);

            const int sel = (int)geti(which_model, b, is64)
                          + ((int)geti(lengths, b, is64) / 17) * 4;

            // layer 1: 16 outputs x 4 lanes (shuffle partners share a warp)
            {
                const int o = lane >> 2;
                const int k = lane & 3;
                const float4* __restrict__ w =
                    (const float4*)(W1 + ((long long)sel * 16 + o) * ACCUM) + k * 16;
                const float4* __restrict__ e = &s_embL[grp][0] + k * 16;
                float s = 0.0f;
                #pragma unroll
                for (int j = 0; j < 16; j++) {
                    float4 wv = w[j], ev = e[j];
                    s += wv.x * ev.x + wv.y * ev.y + wv.z * ev.z + wv.w * ev.w;
                }
                s += __shfl_xor_sync(0xffffffffu, s, 1);
                s += __shfl_xor_sync(0xffffffffu, s, 2);
                if (k == 0) s_h1L[grp][o] = clipped_relu(s + b1[sel * 16 + o]);
            }
            BARX(barid, 64);

            if (lane < 32) {                      // layers 2+3 + epilogue
                const float4* __restrict__ w2 =
                    (const float4*)(W2 + ((long long)sel * 32 + lane) * 16);
                float4 h0 = ((const float4*)s_h1L[grp])[0];
                float4 h1v = ((const float4*)s_h1L[grp])[1];
                float4 h2v = ((const float4*)s_h1L[grp])[2];
                float4 h3v = ((const float4*)s_h1L[grp])[3];
                float4 wa = w2[0], wb = w2[1], wc = w2[2], wd = w2[3];
                float s = b2[sel * 32 + lane]
                    + wa.x * h0.x + wa.y * h0.y + wa.z * h0.z + wa.w * h0.w
                    + wb.x * h1v.x + wb.y * h1v.y + wb.z * h1v.z + wb.w * h1v.w
                    + wc.x * h2v.x + wc.y * h2v.y + wc.z * h2v.z + wc.w * h2v.w
                    + wd.x * h3v.x + wd.y * h3v.y + wd.z * h3v.z + wd.w * h3v.w;
                float p = clipped_relu(s) * W3[sel * 32 + lane];
                #pragma unroll
                for (int off = 16; off > 0; off >>= 1)
                    p += __shfl_xor_sync(0xffffffffu, p, off);
                if (lane == 0) out[b] = tanhf(p + b3[sel] + s_psqtL[grp]);
            }
            // warp B reaches its next s_h1L write only after the next BARX,
            // which warp A joins after finishing layers 2+3 here.
        }
    }
}

extern "C" void kernel_launch(void* const* d_in, const int* in_sizes, int n_in,
                              void* d_out, int out_size) {
    const void*  indices     = d_in[0];
    const void*  offsets     = d_in[1];
    const void*  which_model = d_in[2];
    const void*  lengths     = d_in[3];
    const float* embed       = (const float*)d_in[4];
    const float* bias        = (const float*)d_in[5];
    const float* W1 = (const float*)d_in[6];
    const float* b1 = (const float*)d_in[7];
    const float* W2 = (const float*)d_in[8];
    const float* b2 = (const float*)d_in[9];
    const float* W3 = (const float*)d_in[10];
    const float* b3 = (const float*)d_in[11];

    long long n_idx = in_sizes[0];
    int B = in_sizes[1];

    const int dyn_smem = NSTAGE * 32 * ACCUM * (int)sizeof(__half);  // 96KB
    cudaFuncSetAttribute(nnue_fused,
                         cudaFuncAttributeMaxDynamicSharedMemorySize,
                         dyn_smem);

    convert_kernel<<<2048, 256>>>(embed);
    nnue_fused<<<GRID_MAIN, 384, dyn_smem>>>(indices, offsets, which_model,
                                             lengths, bias,
                                             W1, b1, W2, b2, W3, b3,
                                             (float*)d_out, n_idx, B);
}

// round 17
// speedup vs baseline: 1.0997x; 1.0337x over previous
#include <cuda_runtime.h>
#include <cuda_fp16.h>
#include <cstdint>

#define FEATURE_COUNT 106496LL
#define ACCUM 256
#define LEAK 0.1f
#define NSTAGE 6
#define PF 4
#define GRID_MAIN 296           // 2 blocks/SM on 148-SM B200
#define TMA_NUM 8               // TMA role gets n*8/28 of each chunk

// fp16 copy of the embedding table (54.5 MB module-static scratch)
__device__ __align__(16) __half g_embed_h[FEATURE_COUNT * ACCUM];

__device__ __forceinline__ long long geti(const void* p, long long i, int is64) {
    return is64 ? ((const long long*)p)[i] : (long long)((const int*)p)[i];
}

__device__ __forceinline__ float clipped_relu(float x) {
    float c = fminf(fmaxf(x, -1.0f), 127.0f / 128.0f);
    return c + LEAK * (x - c);
}

__device__ __forceinline__ uint32_t smem_u32(const void* p) {
    uint32_t a;
    asm("{ .reg .u64 t; cvta.to.shared.u64 t, %1; cvt.u32.u64 %0, t; }"
        : "=r"(a) : "l"(p));
    return a;
}

#define BARX(id, cnt) asm volatile("bar.sync %0, %1;" :: "r"(id), "r"(cnt) : "memory")

__device__ __forceinline__ void mbar_wait(uint32_t mbar, int par) {
    uint32_t done;
    asm volatile(
        "{\n\t.reg .pred p;\n\t"
        "mbarrier.try_wait.parity.acquire.cta.shared::cta.b64 p, [%1], %2;\n\t"
        "selp.b32 %0, 1, 0, p;\n\t}"
        : "=r"(done) : "r"(mbar), "r"(par) : "memory");
    while (!done)
        asm volatile(
            "{\n\t.reg .pred p;\n\t"
            "mbarrier.try_wait.parity.acquire.cta.shared::cta.b64 p, [%1], %2, 0x989680;\n\t"
            "selp.b32 %0, 1, 0, p;\n\t}"
            : "=r"(done) : "r"(mbar), "r"(par) : "memory");
}

// accumulate one 16B chunk (8 halves) into 8 fp32 partials
__device__ __forceinline__ void acc8(float* acc, uint4 u) {
    const __half2* h = (const __half2*)&u;
    float2 f0 = __half22float2(h[0]);
    float2 f1 = __half22float2(h[1]);
    float2 f2 = __half22float2(h[2]);
    float2 f3 = __half22float2(h[3]);
    acc[0] += f0.x; acc[1] += f0.y;
    acc[2] += f1.x; acc[3] += f1.y;
    acc[4] += f2.x; acc[5] += f2.y;
    acc[6] += f3.x; acc[7] += f3.y;
}

// ---------------------------------------------------------------------------
// Streaming f32 -> fp16 table conversion (evict_first keeps the 109MB input
// stream out of L2; measured 22us -> 15.6us in R16).
// ---------------------------------------------------------------------------
__global__ __launch_bounds__(256) void convert_kernel(const float* __restrict__ embed) {
    uint64_t pol;
    asm("createpolicy.fractional.L2::evict_first.b64 %0, 1.0;" : "=l"(pol));
    const long long total4 = (FEATURE_COUNT * ACCUM) / 4;
    const float4* __restrict__ e4 = (const float4*)embed;
    uint2* __restrict__ dst = (uint2*)g_embed_h;
    for (long long i = blockIdx.x * (long long)blockDim.x + threadIdx.x;
         i < total4; i += (long long)gridDim.x * blockDim.x) {
        float4 v;
        asm("ld.global.L2::cache_hint.v4.f32 {%0,%1,%2,%3}, [%4], %5;"
            : "=f"(v.x), "=f"(v.y), "=f"(v.z), "=f"(v.w)
            : "l"(e4 + i), "l"(pol));
        __half2 a = __floats2half2_rn(v.x, v.y);
        __half2 b = __floats2half2_rn(v.z, v.w);
        uint2 u;
        u.x = *(uint32_t*)&a;
        u.y = *(uint32_t*)&b;
        dst[i] = u;
    }
}

// ---------------------------------------------------------------------------
// Hybrid kernel on the fp16 table. Request-count-minimized gather:
//   LDG role: ONE warp-LDG.128 per 512B row (32 lanes x uint4 = whole row),
//   two warps per group covering even/odd rows -> 32 warp-requests/batch
//   (was 64). The per-SM request-slot budget is the measured wall; halving
//   requests should halve the LDG-role gather time.
//   TMA role unchanged (1 engine request/row already).
// ---------------------------------------------------------------------------
extern __shared__ __align__(16) __half s_stage_h[];   // NSTAGE*32*256 halves = 96KB

__global__ __launch_bounds__(384, 2) void nnue_fused(
    const void*  __restrict__ indices,
    const void*  __restrict__ offsets,
    const void*  __restrict__ which_model,
    const void*  __restrict__ lengths,
    const float* __restrict__ bias,
    const float* __restrict__ W1, const float* __restrict__ b1,
    const float* __restrict__ W2, const float* __restrict__ b2,
    const float* __restrict__ W3, const float* __restrict__ b3,
    float* __restrict__ out,
    long long n_idx, int B)
{
    __shared__ __align__(8)  unsigned long long s_mbar[NSTAGE];
    __shared__ __align__(16) float  s_embT[ACCUM];
    __shared__ __align__(16) float  s_h1T[16];
    __shared__ __align__(16) float4 s_embL[2][64];
    __shared__ __align__(16) float  s_h1L[2][16];
    __shared__ __align__(16) float  s_part[2][2][ACCUM];   // per-group, per-warp partials
    __shared__ float s_psqtT, s_psqtL[2];
    __shared__ int   s_is64;

    const int t = threadIdx.x;
    const int chunk = (B + (int)gridDim.x - 1) / (int)gridDim.x;
    const int beg = blockIdx.x * chunk;
    const int end = min(beg + chunk, B);
    const int n = end - beg;
    if (n <= 0) return;
    const int nT = (n * TMA_NUM) / 28;   // TMA role's share of the chunk

    // dtype detection (one warp, one ballot) + mbarrier init
    if (t < 32) {
        int ok = 1;
        if (t < 16) {
            long long v = ((const long long*)indices)[t];
            ok = (v >= 0 && v < FEATURE_COUNT);
        }
        unsigned m = __ballot_sync(0xffffffffu, ok);
        if (t == 0) {
            s_is64 = (m == 0xffffffffu) ? 1 : 0;
            #pragma unroll
            for (int s = 0; s < NSTAGE; s++)
                asm volatile("mbarrier.init.shared.b64 [%0], %1;"
                             :: "r"(smem_u32(&s_mbar[s])), "r"(1) : "memory");
        }
    }
    __syncthreads();
    const int is64 = s_is64;

    if (t < 256) {
        // ================= TMA role: batches [beg, beg+nT) =================
        const uint32_t stage_base = smem_u32(s_stage_h);

        auto issue = [&](int i) {
            const int b = beg + i;
            const long long lo = geti(offsets, b, is64);
            const long long hi = (b + 1 < B) ? geti(offsets, b + 1, is64) : n_idx;
            const int st = min((int)(hi - lo), 32);
            const int s = i % NSTAGE;
            const uint32_t mbar = smem_u32(&s_mbar[s]);
            if (t == 0)
                asm volatile("mbarrier.arrive.expect_tx.shared.b64 _, [%0], %1;"
                             :: "r"(mbar), "r"((unsigned)(st * 512)) : "memory");
            __syncwarp();
            if (t < st) {
                long long id = geti(indices, lo + t, is64);
                const __half* src = g_embed_h + id * ACCUM;
                uint32_t dst = stage_base + (uint32_t)s * 16384u + (uint32_t)t * 512u;
                asm volatile(
                    "cp.async.bulk.shared::cta.global.mbarrier::complete_tx::bytes "
                    "[%0], [%1], %2, [%3];"
                    :: "r"(dst), "l"(src), "r"(512), "r"(mbar) : "memory");
            }
        };

        if (t < 32) {
            const int pro = min(PF, nT);
            for (int j = 0; j < pro; j++) issue(j);
        }

        for (int i = 0; i < nT; i++) {
            if (t < 32 && i + PF < nT) issue(i + PF);

            mbar_wait(smem_u32(&s_mbar[i % NSTAGE]), (i / NSTAGE) & 1);

            const int b = beg + i;
            const long long lo = geti(offsets, b, is64);
            const long long hi = (b + 1 < B) ? geti(offsets, b + 1, is64) : n_idx;
            const int cnt = (int)(hi - lo);
            const int staged = min(cnt, 32);
            const __half* __restrict__ st_base = s_stage_h + (i % NSTAGE) * (32 * ACCUM);

            float a0 = bias[t], a1 = 0.0f;
            if (staged == 32) {
                #pragma unroll
                for (int r = 0; r < 32; r += 2) {
                    a0 += __half2float(st_base[r * ACCUM + t]);
                    a1 += __half2float(st_base[(r + 1) * ACCUM + t]);
                }
            } else {
                for (int r = 0; r < staged; r++)
                    a0 += __half2float(st_base[r * ACCUM + t]);
            }
            for (int r = 32; r < cnt; r++) {      // safety tail (L=32: unused)
                long long id = geti(indices, lo + r, is64);
                a0 += __half2float(g_embed_h[id * ACCUM + t]);
            }
            float acc = a0 + a1;

            if (t == 0) s_psqtT = acc;            // pre-activation column 0
            s_embT[t] = clipped_relu(acc);
            BARX(3, 256);

            const int sel = (int)geti(which_model, b, is64)
                          + ((int)geti(lengths, b, is64) / 17) * 4;

            // layer 1: 16 outputs x 16 lanes
            {
                const int o = t >> 4;
                const int k = t & 15;
                const float4* __restrict__ w =
                    (const float4*)(W1 + ((long long)sel * 16 + o) * ACCUM) + k * 4;
                const float4* __restrict__ e = (const float4*)s_embT + k * 4;
                float s = 0.0f;
                #pragma unroll
                for (int j = 0; j < 4; j++) {
                    float4 wv = w[j], ev = e[j];
                    s += wv.x * ev.x + wv.y * ev.y + wv.z * ev.z + wv.w * ev.w;
                }
                s += __shfl_xor_sync(0xffffffffu, s, 1);
                s += __shfl_xor_sync(0xffffffffu, s, 2);
                s += __shfl_xor_sync(0xffffffffu, s, 4);
                s += __shfl_xor_sync(0xffffffffu, s, 8);
                if (k == 0) s_h1T[o] = clipped_relu(s + b1[sel * 16 + o]);
            }
            BARX(3, 256);

            if (t < 32) {                         // layers 2+3 + epilogue
                const float4* __restrict__ w2 =
                    (const float4*)(W2 + ((long long)sel * 32 + t) * 16);
                float4 h0 = ((const float4*)s_h1T)[0];
                float4 h1v = ((const float4*)s_h1T)[1];
                float4 h2v = ((const float4*)s_h1T)[2];
                float4 h3v = ((const float4*)s_h1T)[3];
                float4 wa = w2[0], wb = w2[1], wc = w2[2], wd = w2[3];
                float s = b2[sel * 32 + t]
                    + wa.x * h0.x + wa.y * h0.y + wa.z * h0.z + wa.w * h0.w
                    + wb.x * h1v.x + wb.y * h1v.y + wb.z * h1v.z + wb.w * h1v.w
                    + wc.x * h2v.x + wc.y * h2v.y + wc.z * h2v.z + wc.w * h2v.w
                    + wd.x * h3v.x + wd.y * h3v.y + wd.z * h3v.z + wd.w * h3v.w;
                float p = clipped_relu(s) * W3[sel * 32 + t];
                #pragma unroll
                for (int off = 16; off > 0; off >>= 1)
                    p += __shfl_xor_sync(0xffffffffu, p, off);
                if (t == 0) out[b] = tanhf(p + b3[sel] + s_psqtT);
            }
        }
    } else {
        // ============ LDG role: batches [beg+nT, end), 2 groups ============
        const int gt   = t - 256;      // 0..127
        const int grp  = gt >> 6;      // 0 or 1
        const int lane = gt & 63;      // lane within the 64-thread group
        const int w    = (gt >> 5) & 1;// warp within group (row parity)
        const int wl   = gt & 31;      // lane within warp
        const int barid = 1 + grp;

        for (int b = beg + nT + grp; b < end; b += 2) {
            const long long lo = geti(offsets, b, is64);
            const long long hi = (b + 1 < B) ? geti(offsets, b + 1, is64) : n_idx;
            const int cnt = (int)(hi - lo);
            const int pre = min(cnt, 32);

            // lanes 0..15 preload ids of this warp's rows (parity w)
            int myid = 0;
            {
                int r = w + 2 * wl;
                if (wl < 16 && r < pre) myid = (int)geti(indices, lo + r, is64);
            }

            // one LDG.128 per row: lane wl owns the wl-th 16B chunk (8 cols)
            float acc[8] = {0, 0, 0, 0, 0, 0, 0, 0};
            if (pre == 32) {
                #pragma unroll
                for (int k = 0; k < 16; k++) {
                    int id = __shfl_sync(0xffffffffu, myid, k);
                    uint4 u = *((const uint4*)(g_embed_h + (long long)id * ACCUM) + wl);
                    acc8(acc, u);
                }
            } else {
                for (int k = 0; k < 16; k++) {
                    int r = w + 2 * k;         // uniform per warp
                    if (r >= pre) break;
                    int id = __shfl_sync(0xffffffffu, myid, k);
                    uint4 u = *((const uint4*)(g_embed_h + (long long)id * ACCUM) + wl);
                    acc8(acc, u);
                }
            }
            for (int r = 32 + w; r < cnt; r += 2) {   // safety tail (unused: L=32)
                long long id = geti(indices, lo + r, is64);
                uint4 u = *((const uint4*)(g_embed_h + id * ACCUM) + wl);
                acc8(acc, u);
            }

            // store per-warp partials (cols [8*wl, 8*wl+8))
            {
                float4* p = (float4*)&s_part[grp][w][wl * 8];
                p[0] = make_float4(acc[0], acc[1], acc[2], acc[3]);
                p[1] = make_float4(acc[4], acc[5], acc[6], acc[7]);
            }
            BARX(barid, 64);

            // finalize: lane owns cols [4*lane, 4*lane+4)
            {
                float4 pa = *(const float4*)&s_part[grp][0][4 * lane];
                float4 pb = *(const float4*)&s_part[grp][1][4 * lane];
                float4 bi = ((const float4*)bias)[lane];
                float c0 = pa.x + pb.x + bi.x;
                float c1 = pa.y + pb.y + bi.y;
                float c2 = pa.z + pb.z + bi.z;
                float c3 = pa.w + pb.w + bi.w;
                if (lane == 0) s_psqtL[grp] = c0;   // pre-activation column 0
                s_embL[grp][lane] = make_float4(clipped_relu(c0), clipped_relu(c1),
                                                clipped_relu(c2), clipped_relu(c3));
            }
            BARX(barid, 64);

            const int sel = (int)geti(which_model, b, is64)
                          + ((int)geti(lengths, b, is64) / 17) * 4;

            // layer 1: 16 outputs x 4 lanes (shuffle partners share a warp)
            {
                const int o = lane >> 2;
                const int k = lane & 3;
                const float4* __restrict__ wp =
                    (const float4*)(W1 + ((long long)sel * 16 + o) * ACCUM) + k * 16;
                const float4* __restrict__ e = &s_embL[grp][0] + k * 16;
                float s = 0.0f;
                #pragma unroll
                for (int j = 0; j < 16; j++) {
                    float4 wv = wp[j], ev = e[j];
                    s += wv.x * ev.x + wv.y * ev.y + wv.z * ev.z + wv.w * ev.w;
                }
                s += __shfl_xor_sync(0xffffffffu, s, 1);
                s += __shfl_xor_sync(0xffffffffu, s, 2);
                if (k == 0) s_h1L[grp][o] = clipped_relu(s + b1[sel * 16 + o]);
            }
            BARX(barid, 64);

            if (lane < 32) {                      // layers 2+3 + epilogue
                const float4* __restrict__ w2 =
                    (const float4*)(W2 + ((long long)sel * 32 + lane) * 16);
                float4 h0 = ((const float4*)s_h1L[grp])[0];
                float4 h1v = ((const float4*)s_h1L[grp])[1];
                float4 h2v = ((const float4*)s_h1L[grp])[2];
                float4 h3v = ((const float4*)s_h1L[grp])[3];
                float4 wa = w2[0], wb = w2[1], wc = w2[2], wd = w2[3];
                float s = b2[sel * 32 + lane]
                    + wa.x * h0.x + wa.y * h0.y + wa.z * h0.z + wa.w * h0.w
                    + wb.x * h1v.x + wb.y * h1v.y + wb.z * h1v.z + wb.w * h1v.w
                    + wc.x * h2v.x + wc.y * h2v.y + wc.z * h2v.z + wc.w * h2v.w
                    + wd.x * h3v.x + wd.y * h3v.y + wd.z * h3v.z + wd.w * h3v.w;
                float p = clipped_relu(s) * W3[sel * 32 + lane];
                #pragma unroll
                for (int off = 16; off > 0; off >>= 1)
                    p += __shfl_xor_sync(0xffffffffu, p, off);
                if (lane == 0) out[b] = tanhf(p + b3[sel] + s_psqtL[grp]);
            }
            // s_part/s_embL/s_h1L reuse across iterations is ordered by the
            // three BARX points (see R6 analysis; structure unchanged).
        }
    }
}

extern "C" void kernel_launch(void* const* d_in, const int* in_sizes, int n_in,
                              void* d_out, int out_size) {
    const void*  indices     = d_in[0];
    const void*  offsets     = d_in[1];
    const void*  which_model = d_in[2];
    const void*  lengths     = d_in[3];
    const float* embed       = (const float*)d_in[4];
    const float* bias        = (const float*)d_in[5];
    const float* W1 = (const float*)d_in[6];
    const float* b1 = (const float*)d_in[7];
    const float* W2 = (const float*)d_in[8];
    const float* b2 = (const float*)d_in[9];
    const float* W3 = (const float*)d_in[10];
    const float* b3 = (const float*)d_in[11];

    long long n_idx = in_sizes[0];
    int B = in_sizes[1];

    const int dyn_smem = NSTAGE * 32 * ACCUM * (int)sizeof(__half);  // 96KB
    cudaFuncSetAttribute(nnue_fused,
                         cudaFuncAttributeMaxDynamicSharedMemorySize,
                         dyn_smem);

    convert_kernel<<<2048, 256>>>(embed);
    nnue_fused<<<GRID_MAIN, 384, dyn_smem>>>(indices, offsets, which_model,
                                             lengths, bias,
                                             W1, b1, W2, b2, W3, b3,
                                             (float*)d_out, n_idx, B);
}